// round 16
// baseline (speedup 1.0000x reference)
#include <cuda_runtime.h>
#include <cuda_fp16.h>
#include <cstdint>

#define N_NODES 8192
#define M_NBR   16
#define F_NODE  128
#define HID     512

// ---------------- scratch (__device__ globals; no allocations) ----------------
__device__ __half g_HA[N_NODES * HID];   // activation ping
__device__ __half g_HB[N_NODES * HID];   // activation pong
__device__ float  g_dinv[N_NODES];
#define WOFF_1 0
#define WOFF_2 (HID * HID)
#define WOFF_3 (2 * HID * HID)
#define WOFF_E (3 * HID * HID)
__device__ __half g_W[3 * HID * HID + HID * F_NODE];

// ---------------- PTX helpers (compute_103-safe) ----------------
__device__ __forceinline__ uint32_t smem_to_u32(const void* p) {
    uint32_t a;
    asm("{ .reg .u64 t; cvta.to.shared.u64 t, %1; cvt.u32.u64 %0, t; }" : "=r"(a) : "l"(p));
    return a;
}
__device__ __forceinline__ void cp_async16(uint32_t saddr, const void* gptr) {
    asm volatile("cp.async.cg.shared.global [%0], [%1], 16;" :: "r"(saddr), "l"(gptr));
}
#define CP_COMMIT() asm volatile("cp.async.commit_group;" ::: "memory")
#define CP_WAIT0()  asm volatile("cp.async.wait_group 0;" ::: "memory")
#define CP_WAIT1()  asm volatile("cp.async.wait_group 1;" ::: "memory")

__device__ __forceinline__ void ldsm_x4(uint32_t& r0, uint32_t& r1, uint32_t& r2,
                                        uint32_t& r3, uint32_t addr) {
    asm volatile("ldmatrix.sync.aligned.m8n8.x4.shared.b16 {%0,%1,%2,%3}, [%4];"
                 : "=r"(r0), "=r"(r1), "=r"(r2), "=r"(r3) : "r"(addr));
}
__device__ __forceinline__ void mma16816(float* d, const uint32_t* a, const uint32_t* b) {
    asm volatile(
        "mma.sync.aligned.m16n8k16.row.col.f32.f16.f16.f32 "
        "{%0,%1,%2,%3}, {%4,%5,%6,%7}, {%8,%9}, {%0,%1,%2,%3};"
        : "+f"(d[0]), "+f"(d[1]), "+f"(d[2]), "+f"(d[3])
        : "r"(a[0]), "r"(a[1]), "r"(a[2]), "r"(a[3]), "r"(b[0]), "r"(b[1]));
}

// ---------------------------------------------------------------------------
// Fused preprocessing (one launch) — unchanged from R9.
// ---------------------------------------------------------------------------
#define PREP_DEG    32
#define PREP_CONV   1024
#define PREP_WE     64
#define PREP_W3     768
#define PREP_BLOCKS (PREP_DEG + PREP_CONV + PREP_WE + PREP_W3)

__device__ __forceinline__ void wconv_tile(const float* __restrict__ W, int K, int N,
                                           __half* __restrict__ o,
                                           int n0, int k0, int tx, int ty,
                                           float (*tile)[33]) {
#pragma unroll
    for (int r = 0; r < 4; r++) {
        int k = k0 + ty + r * 8;
        tile[ty + r * 8][tx] = W[(size_t)k * N + n0 + tx];
    }
    __syncthreads();
#pragma unroll
    for (int r = 0; r < 4; r++) {
        int n = ty + r * 8;
        o[(size_t)(n0 + n) * K + k0 + tx] = __float2half_rn(tile[tx][n]);
    }
}

__global__ __launch_bounds__(256) void prep_kernel(const int* __restrict__ idx,
                                                   const float* __restrict__ node_in,
                                                   const float* __restrict__ W_emb,
                                                   const float* __restrict__ W1,
                                                   const float* __restrict__ W2,
                                                   const float* __restrict__ W3) {
    __shared__ float tile[32][33];
    const int b = blockIdx.x;
    const int tid = threadIdx.x;

    if (b < PREP_DEG) {
        int i = b * 256 + tid;
        int cnt = 1;
#pragma unroll
        for (int k = 0; k < M_NBR; k++) cnt += (idx[i * M_NBR + k] >= 0) ? 1 : 0;
        g_dinv[i] = rsqrtf((float)cnt);
    } else if (b < PREP_DEG + PREP_CONV) {
        int c4 = (b - PREP_DEG) * 256 + tid;
        float4 v = ((const float4*)node_in)[c4];
        __half2 h0 = __floats2half2_rn(v.x, v.y);
        __half2 h1 = __floats2half2_rn(v.z, v.w);
        uint2 o;
        o.x = *(uint32_t*)&h0;
        o.y = *(uint32_t*)&h1;
        ((uint2*)g_HA)[c4] = o;
    } else if (b < PREP_DEG + PREP_CONV + PREP_WE) {
        int t = b - (PREP_DEG + PREP_CONV);
        int n0 = (t & 15) * 32, k0 = (t >> 4) * 32;
        wconv_tile(W_emb, F_NODE, HID, g_W + WOFF_E, n0, k0, tid & 31, tid >> 5, tile);
    } else {
        int t = b - (PREP_DEG + PREP_CONV + PREP_WE);
        int z = t >> 8;
        int tt = t & 255;
        int n0 = (tt & 15) * 32, k0 = (tt >> 4) * 32;
        const float* W = (z == 0) ? W1 : (z == 1) ? W2 : W3;
        wconv_tile(W, HID, HID, g_W + (size_t)z * HID * HID, n0, k0,
                   tid & 31, tid >> 5, tile);
    }
}

// ---------------------------------------------------------------------------
// SpMM — R9's exact uint4 version (4 rows x 64 lanes, 16B per lane).
// ---------------------------------------------------------------------------
__global__ __launch_bounds__(256) void spmm_kernel(const int* __restrict__ idx,
                                                   const __half* __restrict__ Xin,
                                                   __half* __restrict__ Xout) {
    const int rloc = threadIdx.x >> 6;
    const int t64 = threadIdx.x & 63;
    const int i = blockIdx.x * 4 + rloc;

    __shared__ int s_j[4][M_NBR];
    __shared__ float s_dj[4][M_NBR];
    if (t64 < M_NBR) {
        int j = idx[i * M_NBR + t64];
        s_j[rloc][t64] = (j >= 0) ? j : 0;
        s_dj[rloc][t64] = (j >= 0) ? g_dinv[j] : 0.0f;
    }
    __syncthreads();

    const float di = g_dinv[i];
    float acc[8];
    {
        uint4 v = ((const uint4*)(Xin + (size_t)i * HID))[t64];
        float2 p0 = __half22float2(*(__half2*)&v.x);
        float2 p1 = __half22float2(*(__half2*)&v.y);
        float2 p2 = __half22float2(*(__half2*)&v.z);
        float2 p3 = __half22float2(*(__half2*)&v.w);
        acc[0] = p0.x * di; acc[1] = p0.y * di;
        acc[2] = p1.x * di; acc[3] = p1.y * di;
        acc[4] = p2.x * di; acc[5] = p2.y * di;
        acc[6] = p3.x * di; acc[7] = p3.y * di;
    }

#pragma unroll
    for (int k = 0; k < M_NBR; k++) {
        const int j = s_j[rloc][k];
        const float dj = s_dj[rloc][k];
        uint4 v = ((const uint4*)(Xin + (size_t)j * HID))[t64];
        float2 p0 = __half22float2(*(__half2*)&v.x);
        float2 p1 = __half22float2(*(__half2*)&v.y);
        float2 p2 = __half22float2(*(__half2*)&v.z);
        float2 p3 = __half22float2(*(__half2*)&v.w);
        acc[0] += dj * p0.x; acc[1] += dj * p0.y;
        acc[2] += dj * p1.x; acc[3] += dj * p1.y;
        acc[4] += dj * p2.x; acc[5] += dj * p2.y;
        acc[6] += dj * p3.x; acc[7] += dj * p3.y;
    }

    uint4 o;
    __half2 h0 = __floats2half2_rn(acc[0] * di, acc[1] * di);
    __half2 h1 = __floats2half2_rn(acc[2] * di, acc[3] * di);
    __half2 h2 = __floats2half2_rn(acc[4] * di, acc[5] * di);
    __half2 h3 = __floats2half2_rn(acc[6] * di, acc[7] * di);
    o.x = *(uint32_t*)&h0;
    o.y = *(uint32_t*)&h1;
    o.z = *(uint32_t*)&h2;
    o.w = *(uint32_t*)&h3;
    ((uint4*)(Xout + (size_t)i * HID))[t64] = o;
}

// ---------------------------------------------------------------------------
// fp16 HMMA GEMM, occupancy-oriented: BM=64 BN=128 BK=64, 256 thr,
// warp grid 2x4, warp tile 32x32, 2-stage cp.async, 3 CTAs/SM target.
// ---------------------------------------------------------------------------
#define BM 64
#define BN 128
#define BK 64
#define GTHR 256
#define ROWB 144                        // 64*2 + 16 pad bytes
#define STAGE_B ((BM + BN) * ROWB)      // 27648 B per stage
#define GSMEM   (2 * STAGE_B)           // 55296 B

template <int K, bool HALF_OUT>
__global__ __launch_bounds__(GTHR, 3)
void gemm_hmma_kernel(const __half* __restrict__ A,
                      const __half* __restrict__ B,
                      const float* __restrict__ bias,
                      void* __restrict__ Cout, int relu) {
    extern __shared__ __align__(16) char dynsmem[];

    const int tid = threadIdx.x;
    const int lane = tid & 31;
    const int wid = tid >> 5;
    const int warp_m = wid >> 2;   // 0..1 (32-row band)
    const int warp_n = wid & 3;    // 0..3 (32-col band)
    const int m0 = blockIdx.y * BM;
    const int n0 = blockIdx.x * BN;

    uint32_t sA[2], sB[2];
#pragma unroll
    for (int s = 0; s < 2; s++) {
        sA[s] = smem_to_u32(dynsmem + s * STAGE_B);
        sB[s] = sA[s] + BM * ROWB;
    }

    float acc[2][4][4];
#pragma unroll
    for (int i = 0; i < 2; i++)
#pragma unroll
        for (int j = 0; j < 4; j++)
#pragma unroll
            for (int q = 0; q < 4; q++) acc[i][j][q] = 0.0f;

    constexpr int KT = K / BK;

    const int mat = lane >> 3;
    const int mrow = lane & 7;
    const int a_row = warp_m * 32 + ((mat & 1) << 3) + mrow;
    const int a_koff = (mat >> 1) << 3;
    const int b_row = warp_n * 32 + ((mat >> 1) << 3) + mrow;
    const int b_koff = (mat & 1) << 3;

    // loads: A 64 rows x 8 chunks = 512 (2/thr); B 128 x 8 = 1024 (4/thr)
    const int lr = tid >> 3;        // 0..31
    const int lc = tid & 7;         // 0..7

#define LOAD_STAGE(kt, buf)                                                     \
    do {                                                                        \
        const int kk_ = (kt) * BK;                                              \
        _Pragma("unroll")                                                       \
        for (int s_ = 0; s_ < 2; s_++) {                                        \
            int r_ = lr + s_ * 32;                                              \
            cp_async16(sA[buf] + r_ * ROWB + lc * 16,                           \
                       A + (size_t)(m0 + r_) * K + kk_ + lc * 8);               \
        }                                                                       \
        _Pragma("unroll")                                                       \
        for (int s_ = 0; s_ < 4; s_++) {                                        \
            int r_ = lr + s_ * 32;                                              \
            cp_async16(sB[buf] + r_ * ROWB + lc * 16,                           \
                       B + (size_t)(n0 + r_) * K + kk_ + lc * 8);               \
        }                                                                       \
    } while (0)

    LOAD_STAGE(0, 0);
    CP_COMMIT();

    for (int kt = 0; kt < KT; kt++) {
        const int buf = kt & 1;
        if (kt + 1 < KT) {
            LOAD_STAGE(kt + 1, buf ^ 1);
            CP_COMMIT();
            CP_WAIT1();
        } else {
            CP_WAIT0();
        }
        __syncthreads();

#pragma unroll
        for (int ks = 0; ks < BK / 16; ks++) {
            uint32_t af[2][4];
#pragma unroll
            for (int mt = 0; mt < 2; mt++) {
                uint32_t addr = sA[buf] + (a_row + mt * 16) * ROWB +
                                (ks * 16 + a_koff) * 2;
                ldsm_x4(af[mt][0], af[mt][1], af[mt][2], af[mt][3], addr);
            }
            uint32_t bfr[4][2];
#pragma unroll
            for (int p = 0; p < 2; p++) {
                uint32_t r0, r1, r2, r3;
                uint32_t addr = sB[buf] + (b_row + p * 16) * ROWB +
                                (ks * 16 + b_koff) * 2;
                ldsm_x4(r0, r1, r2, r3, addr);
                bfr[2 * p][0] = r0; bfr[2 * p][1] = r1;
                bfr[2 * p + 1][0] = r2; bfr[2 * p + 1][1] = r3;
            }
#pragma unroll
            for (int mt = 0; mt < 2; mt++)
#pragma unroll
                for (int nt = 0; nt < 4; nt++)
                    mma16816(acc[mt][nt], af[mt], bfr[nt]);
        }
        __syncthreads();   // protect buf before it is overwritten next iter
    }

    // epilogue
#pragma unroll
    for (int mt = 0; mt < 2; mt++) {
        const int rm = m0 + warp_m * 32 + mt * 16 + (lane >> 2);
#pragma unroll
        for (int nt = 0; nt < 4; nt++) {
            const int cn = n0 + warp_n * 32 + nt * 8 + ((lane & 3) << 1);
            const float b0 = bias[cn], b1 = bias[cn + 1];
            float2 v0, v1;
            v0.x = acc[mt][nt][0] + b0;
            v0.y = acc[mt][nt][1] + b1;
            v1.x = acc[mt][nt][2] + b0;
            v1.y = acc[mt][nt][3] + b1;
            if (relu) {
                v0.x = fmaxf(v0.x, 0.0f); v0.y = fmaxf(v0.y, 0.0f);
                v1.x = fmaxf(v1.x, 0.0f); v1.y = fmaxf(v1.y, 0.0f);
            }
            if (HALF_OUT) {
                __half* Ch = (__half*)Cout;
                *(__half2*)&Ch[(size_t)rm * HID + cn] = __floats2half2_rn(v0.x, v0.y);
                *(__half2*)&Ch[(size_t)(rm + 8) * HID + cn] = __floats2half2_rn(v1.x, v1.y);
            } else {
                float* Cf = (float*)Cout;
                *(float2*)&Cf[(size_t)rm * HID + cn] = v0;
                *(float2*)&Cf[(size_t)(rm + 8) * HID + cn] = v1;
            }
        }
    }
}

// ---------------------------------------------------------------------------
extern "C" void kernel_launch(void* const* d_in, const int* in_sizes, int n_in,
                              void* d_out, int out_size) {
    const float* node_in = (const float*)d_in[0];
    const int*   edges   = (const int*)d_in[1];
    const float* W_emb   = (const float*)d_in[2];
    const float* b_emb   = (const float*)d_in[3];
    const float* W1      = (const float*)d_in[4];
    const float* b1      = (const float*)d_in[5];
    const float* W2      = (const float*)d_in[6];
    const float* b2      = (const float*)d_in[7];
    const float* W3      = (const float*)d_in[8];
    const float* b3      = (const float*)d_in[9];
    float* out = (float*)d_out;

    __half* HA; cudaGetSymbolAddress((void**)&HA, g_HA);
    __half* HB; cudaGetSymbolAddress((void**)&HB, g_HB);
    __half* W;  cudaGetSymbolAddress((void**)&W, g_W);

    cudaFuncSetAttribute(gemm_hmma_kernel<HID, true>,
                         cudaFuncAttributeMaxDynamicSharedMemorySize, GSMEM);
    cudaFuncSetAttribute(gemm_hmma_kernel<HID, false>,
                         cudaFuncAttributeMaxDynamicSharedMemorySize, GSMEM);
    cudaFuncSetAttribute(gemm_hmma_kernel<F_NODE, true>,
                         cudaFuncAttributeMaxDynamicSharedMemorySize, GSMEM);

    prep_kernel<<<PREP_BLOCKS, 256>>>(edges, node_in, W_emb, W1, W2, W3);

    dim3 gg(HID / BN, N_NODES / BM);  // (4, 128) = 512 CTAs
    dim3 sg(N_NODES / 4);             // 2048 blocks

    // embed: HB = node_in @ W_emb + b_emb  (fp16 out)
    gemm_hmma_kernel<F_NODE, true><<<gg, GTHR, GSMEM>>>(HA, W + WOFF_E, b_emb, HB, 0);
    // layer 1
    spmm_kernel<<<sg, 256>>>(edges, HB, HA);
    gemm_hmma_kernel<HID, true><<<gg, GTHR, GSMEM>>>(HA, W + WOFF_1, b1, HB, 1);
    // layer 2
    spmm_kernel<<<sg, 256>>>(edges, HB, HA);
    gemm_hmma_kernel<HID, true><<<gg, GTHR, GSMEM>>>(HA, W + WOFF_2, b2, HB, 1);
    // layer 3 -> fp32 out
    spmm_kernel<<<sg, 256>>>(edges, HB, HA);
    gemm_hmma_kernel<HID, false><<<gg, GTHR, GSMEM>>>(HA, W + WOFF_3, b3, out, 0);
}

// round 17
// speedup vs baseline: 1.0886x; 1.0886x over previous
#include <cuda_runtime.h>
#include <cuda_fp16.h>
#include <cstdint>

#define N_NODES 8192
#define M_NBR   16
#define F_NODE  128
#define HID     512

// ---------------- scratch (__device__ globals; no allocations) ----------------
__device__ __half g_HA[N_NODES * HID];   // activation ping
__device__ __half g_HB[N_NODES * HID];   // activation pong
__device__ float  g_dinv[N_NODES];
#define WOFF_1 0
#define WOFF_2 (HID * HID)
#define WOFF_3 (2 * HID * HID)
#define WOFF_E (3 * HID * HID)
__device__ __half g_W[3 * HID * HID + HID * F_NODE];

// ---------------- PTX helpers (compute_103-safe) ----------------
__device__ __forceinline__ uint32_t smem_to_u32(const void* p) {
    uint32_t a;
    asm("{ .reg .u64 t; cvta.to.shared.u64 t, %1; cvt.u32.u64 %0, t; }" : "=r"(a) : "l"(p));
    return a;
}
__device__ __forceinline__ void cp_async16(uint32_t saddr, const void* gptr) {
    asm volatile("cp.async.cg.shared.global [%0], [%1], 16;" :: "r"(saddr), "l"(gptr));
}
#define CP_COMMIT() asm volatile("cp.async.commit_group;" ::: "memory")
#define CP_WAIT0()  asm volatile("cp.async.wait_group 0;" ::: "memory")
#define CP_WAIT1()  asm volatile("cp.async.wait_group 1;" ::: "memory")

__device__ __forceinline__ void ldsm_x4(uint32_t& r0, uint32_t& r1, uint32_t& r2,
                                        uint32_t& r3, uint32_t addr) {
    asm volatile("ldmatrix.sync.aligned.m8n8.x4.shared.b16 {%0,%1,%2,%3}, [%4];"
                 : "=r"(r0), "=r"(r1), "=r"(r2), "=r"(r3) : "r"(addr));
}
__device__ __forceinline__ void mma16816(float* d, const uint32_t* a, const uint32_t* b) {
    asm volatile(
        "mma.sync.aligned.m16n8k16.row.col.f32.f16.f16.f32 "
        "{%0,%1,%2,%3}, {%4,%5,%6,%7}, {%8,%9}, {%0,%1,%2,%3};"
        : "+f"(d[0]), "+f"(d[1]), "+f"(d[2]), "+f"(d[3])
        : "r"(a[0]), "r"(a[1]), "r"(a[2]), "r"(a[3]), "r"(b[0]), "r"(b[1]));
}

// ---------------------------------------------------------------------------
// Transpose tile helper: W[K][N] fp32 -> o[N][K] fp16, scratch provided.
// ---------------------------------------------------------------------------
__device__ __forceinline__ void wconv_tile(const float* __restrict__ W, int K, int N,
                                           __half* __restrict__ o,
                                           int n0, int k0, int tx, int ty,
                                           float (*tile)[33]) {
#pragma unroll
    for (int r = 0; r < 4; r++) {
        int k = k0 + ty + r * 8;
        tile[ty + r * 8][tx] = W[(size_t)k * N + n0 + tx];
    }
    __syncthreads();
#pragma unroll
    for (int r = 0; r < 4; r++) {
        int n = ty + r * 8;
        o[(size_t)(n0 + n) * K + k0 + tx] = __float2half_rn(tile[tx][n]);
    }
}

// ---------------------------------------------------------------------------
// Prep (one launch): deg + input conversion + W_emb transpose only.
//   [0,32)      deg -> dinv
//   [32,1056)   node_in fp32 -> g_HA fp16
//   [1056,1120) W_emb transpose -> g_W[WOFF_E]
// ---------------------------------------------------------------------------
#define PREP_DEG    32
#define PREP_CONV   1024
#define PREP_WE     64
#define PREP_BLOCKS (PREP_DEG + PREP_CONV + PREP_WE)

__global__ __launch_bounds__(256) void prep_kernel(const int* __restrict__ idx,
                                                   const float* __restrict__ node_in,
                                                   const float* __restrict__ W_emb) {
    __shared__ float tile[32][33];
    const int b = blockIdx.x;
    const int tid = threadIdx.x;

    if (b < PREP_DEG) {
        int i = b * 256 + tid;
        int cnt = 1;
#pragma unroll
        for (int k = 0; k < M_NBR; k++) cnt += (idx[i * M_NBR + k] >= 0) ? 1 : 0;
        g_dinv[i] = rsqrtf((float)cnt);
    } else if (b < PREP_DEG + PREP_CONV) {
        int c4 = (b - PREP_DEG) * 256 + tid;
        float4 v = ((const float4*)node_in)[c4];
        __half2 h0 = __floats2half2_rn(v.x, v.y);
        __half2 h1 = __floats2half2_rn(v.z, v.w);
        uint2 o;
        o.x = *(uint32_t*)&h0;
        o.y = *(uint32_t*)&h1;
        ((uint2*)g_HA)[c4] = o;
    } else {
        int t = b - (PREP_DEG + PREP_CONV);
        int n0 = (t & 15) * 32, k0 = (t >> 4) * 32;
        wconv_tile(W_emb, F_NODE, HID, g_W + WOFF_E, n0, k0, tid & 31, tid >> 5, tile);
    }
}

// ---------------------------------------------------------------------------
// GEMM body (R9 kernel, device function). BM=128 BN=128 BK=64, 256 thr,
// warp grid 2x4 (warp tile 64x32), 3-stage cp.async.
// ---------------------------------------------------------------------------
#define BM 128
#define BN 128
#define BK 64
#define GTHR 256
#define ROWB 144
#define STAGE_B (2 * BM * ROWB)
#define GSMEM   (3 * STAGE_B)

template <int K, bool HALF_OUT>
__device__ __forceinline__ void gemm_body(int bx, int by,
                                          const __half* __restrict__ A,
                                          const __half* __restrict__ B,
                                          const float* __restrict__ bias,
                                          void* __restrict__ Cout, int relu,
                                          char* dynsmem) {
    const int tid = threadIdx.x;
    const int lane = tid & 31;
    const int wid = tid >> 5;
    const int warp_m = wid >> 2;
    const int warp_n = wid & 3;
    const int m0 = by * BM;
    const int n0 = bx * BN;

    uint32_t sA[3], sB[3];
#pragma unroll
    for (int s = 0; s < 3; s++) {
        sA[s] = smem_to_u32(dynsmem + s * STAGE_B);
        sB[s] = sA[s] + BM * ROWB;
    }

    float acc[4][4][4];
#pragma unroll
    for (int i = 0; i < 4; i++)
#pragma unroll
        for (int j = 0; j < 4; j++)
#pragma unroll
            for (int q = 0; q < 4; q++) acc[i][j][q] = 0.0f;

    constexpr int KT = K / BK;

    const int mat = lane >> 3;
    const int mrow = lane & 7;
    const int a_row = warp_m * 64 + ((mat & 1) << 3) + mrow;
    const int a_koff = (mat >> 1) << 3;
    const int b_row = warp_n * 32 + ((mat >> 1) << 3) + mrow;
    const int b_koff = (mat & 1) << 3;

    const int lr = tid >> 3;
    const int lc = tid & 7;

#define LOAD_STAGE(kt, buf)                                                     \
    do {                                                                        \
        const int kk_ = (kt) * BK;                                              \
        _Pragma("unroll")                                                       \
        for (int s_ = 0; s_ < 4; s_++) {                                        \
            int r_ = lr + s_ * 32;                                              \
            cp_async16(sA[buf] + r_ * ROWB + lc * 16,                           \
                       A + (size_t)(m0 + r_) * K + kk_ + lc * 8);               \
            cp_async16(sB[buf] + r_ * ROWB + lc * 16,                           \
                       B + (size_t)(n0 + r_) * K + kk_ + lc * 8);               \
        }                                                                       \
    } while (0)

    LOAD_STAGE(0, 0);
    CP_COMMIT();
    LOAD_STAGE(1, 1);
    CP_COMMIT();

    for (int kt = 0; kt < KT; kt++) {
        const int buf = kt % 3;
        if (kt + 1 < KT) CP_WAIT1(); else CP_WAIT0();
        __syncthreads();
        if (kt + 2 < KT) {
            LOAD_STAGE(kt + 2, (kt + 2) % 3);
            CP_COMMIT();
        }

#pragma unroll
        for (int ks = 0; ks < BK / 16; ks++) {
            uint32_t af[4][4];
#pragma unroll
            for (int mt = 0; mt < 4; mt++) {
                uint32_t addr = sA[buf] + (a_row + mt * 16) * ROWB +
                                (ks * 16 + a_koff) * 2;
                ldsm_x4(af[mt][0], af[mt][1], af[mt][2], af[mt][3], addr);
            }
            uint32_t bfr[4][2];
#pragma unroll
            for (int p = 0; p < 2; p++) {
                uint32_t r0, r1, r2, r3;
                uint32_t addr = sB[buf] + (b_row + p * 16) * ROWB +
                                (ks * 16 + b_koff) * 2;
                ldsm_x4(r0, r1, r2, r3, addr);
                bfr[2 * p][0] = r0; bfr[2 * p][1] = r1;
                bfr[2 * p + 1][0] = r2; bfr[2 * p + 1][1] = r3;
            }
#pragma unroll
            for (int mt = 0; mt < 4; mt++)
#pragma unroll
                for (int nt = 0; nt < 4; nt++)
                    mma16816(acc[mt][nt], af[mt], bfr[nt]);
        }
    }

#pragma unroll
    for (int mt = 0; mt < 4; mt++) {
        const int rm = m0 + warp_m * 64 + mt * 16 + (lane >> 2);
#pragma unroll
        for (int nt = 0; nt < 4; nt++) {
            const int cn = n0 + warp_n * 32 + nt * 8 + ((lane & 3) << 1);
            const float b0 = bias[cn], b1 = bias[cn + 1];
            float2 v0, v1;
            v0.x = acc[mt][nt][0] + b0;
            v0.y = acc[mt][nt][1] + b1;
            v1.x = acc[mt][nt][2] + b0;
            v1.y = acc[mt][nt][3] + b1;
            if (relu) {
                v0.x = fmaxf(v0.x, 0.0f); v0.y = fmaxf(v0.y, 0.0f);
                v1.x = fmaxf(v1.x, 0.0f); v1.y = fmaxf(v1.y, 0.0f);
            }
            if (HALF_OUT) {
                __half* Ch = (__half*)Cout;
                *(__half2*)&Ch[(size_t)rm * HID + cn] = __floats2half2_rn(v0.x, v0.y);
                *(__half2*)&Ch[(size_t)(rm + 8) * HID + cn] = __floats2half2_rn(v1.x, v1.y);
            } else {
                float* Cf = (float*)Cout;
                *(float2*)&Cf[(size_t)rm * HID + cn] = v0;
                *(float2*)&Cf[(size_t)(rm + 8) * HID + cn] = v1;
            }
        }
    }
}

// Plain GEMM wrapper (layers 2/3)
template <int K, bool HALF_OUT>
__global__ __launch_bounds__(GTHR, 2)
void gemm_hmma_kernel(const __half* __restrict__ A,
                      const __half* __restrict__ B,
                      const float* __restrict__ bias,
                      void* __restrict__ Cout, int relu) {
    extern __shared__ __align__(16) char dynsmem[];
    gemm_body<K, HALF_OUT>(blockIdx.x, blockIdx.y, A, B, bias, Cout, relu, dynsmem);
}

// Fused: embed GEMM (blocks 0..255) + W1/W2/W3 transposes (blocks 256..1023)
#define EMBW_GEMM_BLOCKS 256
#define EMBW_BLOCKS (EMBW_GEMM_BLOCKS + 768)

__global__ __launch_bounds__(GTHR, 2)
void embw_kernel(const __half* __restrict__ HA,
                 const __half* __restrict__ WeT,
                 const float* __restrict__ b_emb,
                 __half* __restrict__ HB,
                 const float* __restrict__ W1,
                 const float* __restrict__ W2,
                 const float* __restrict__ W3,
                 __half* __restrict__ Wout) {
    extern __shared__ __align__(16) char dynsmem[];
    const int b = blockIdx.x;
    if (b < EMBW_GEMM_BLOCKS) {
        gemm_body<F_NODE, true>(b & 3, b >> 2, HA, WeT, b_emb, HB, 0, dynsmem);
    } else {
        int t = b - EMBW_GEMM_BLOCKS;
        int z = t >> 8;                 // 0..2
        int tt = t & 255;
        int n0 = (tt & 15) * 32, k0 = (tt >> 4) * 32;
        const float* W = (z == 0) ? W1 : (z == 1) ? W2 : W3;
        float (*tile)[33] = (float (*)[33])dynsmem;
        wconv_tile(W, HID, HID, Wout + (size_t)z * HID * HID, n0, k0,
                   threadIdx.x & 31, threadIdx.x >> 5, tile);
    }
}

// ---------------------------------------------------------------------------
// SpMM (fp16 in/out, fp32 accumulate), folded coefficients:
//   y[i,:] = di^2 * x_i + sum_k (di*dj_k) * x_jk    (no final scale pass)
// 256 thr = 4 rows x 64 lanes, uint4 per lane (R9 geometry).
// ---------------------------------------------------------------------------
__global__ __launch_bounds__(256) void spmm_kernel(const int* __restrict__ idx,
                                                   const __half* __restrict__ Xin,
                                                   __half* __restrict__ Xout) {
    const int rloc = threadIdx.x >> 6;
    const int t64 = threadIdx.x & 63;
    const int i = blockIdx.x * 4 + rloc;

    __shared__ int s_j[4][M_NBR];
    __shared__ float s_c[4][M_NBR];
    if (t64 < M_NBR) {
        int j = idx[i * M_NBR + t64];
        float di = g_dinv[i];
        s_j[rloc][t64] = (j >= 0) ? j : 0;
        s_c[rloc][t64] = (j >= 0) ? di * g_dinv[j] : 0.0f;
    }
    __syncthreads();

    const float di = g_dinv[i];
    const float cii = di * di;
    float acc[8];
    {
        uint4 v = ((const uint4*)(Xin + (size_t)i * HID))[t64];
        float2 p0 = __half22float2(*(__half2*)&v.x);
        float2 p1 = __half22float2(*(__half2*)&v.y);
        float2 p2 = __half22float2(*(__half2*)&v.z);
        float2 p3 = __half22float2(*(__half2*)&v.w);
        acc[0] = p0.x * cii; acc[1] = p0.y * cii;
        acc[2] = p1.x * cii; acc[3] = p1.y * cii;
        acc[4] = p2.x * cii; acc[5] = p2.y * cii;
        acc[6] = p3.x * cii; acc[7] = p3.y * cii;
    }

#pragma unroll
    for (int k = 0; k < M_NBR; k++) {
        const int j = s_j[rloc][k];
        const float c = s_c[rloc][k];
        uint4 v = ((const uint4*)(Xin + (size_t)j * HID))[t64];
        float2 p0 = __half22float2(*(__half2*)&v.x);
        float2 p1 = __half22float2(*(__half2*)&v.y);
        float2 p2 = __half22float2(*(__half2*)&v.z);
        float2 p3 = __half22float2(*(__half2*)&v.w);
        acc[0] += c * p0.x; acc[1] += c * p0.y;
        acc[2] += c * p1.x; acc[3] += c * p1.y;
        acc[4] += c * p2.x; acc[5] += c * p2.y;
        acc[6] += c * p3.x; acc[7] += c * p3.y;
    }

    uint4 o;
    __half2 h0 = __floats2half2_rn(acc[0], acc[1]);
    __half2 h1 = __floats2half2_rn(acc[2], acc[3]);
    __half2 h2 = __floats2half2_rn(acc[4], acc[5]);
    __half2 h3 = __floats2half2_rn(acc[6], acc[7]);
    o.x = *(uint32_t*)&h0;
    o.y = *(uint32_t*)&h1;
    o.z = *(uint32_t*)&h2;
    o.w = *(uint32_t*)&h3;
    ((uint4*)(Xout + (size_t)i * HID))[t64] = o;
}

// ---------------------------------------------------------------------------
extern "C" void kernel_launch(void* const* d_in, const int* in_sizes, int n_in,
                              void* d_out, int out_size) {
    const float* node_in = (const float*)d_in[0];
    const int*   edges   = (const int*)d_in[1];
    const float* W_emb   = (const float*)d_in[2];
    const float* b_emb   = (const float*)d_in[3];
    const float* W1      = (const float*)d_in[4];
    const float* b1      = (const float*)d_in[5];
    const float* W2      = (const float*)d_in[6];
    const float* b2      = (const float*)d_in[7];
    const float* W3      = (const float*)d_in[8];
    const float* b3      = (const float*)d_in[9];
    float* out = (float*)d_out;

    __half* HA; cudaGetSymbolAddress((void**)&HA, g_HA);
    __half* HB; cudaGetSymbolAddress((void**)&HB, g_HB);
    __half* W;  cudaGetSymbolAddress((void**)&W, g_W);

    cudaFuncSetAttribute(gemm_hmma_kernel<HID, true>,
                         cudaFuncAttributeMaxDynamicSharedMemorySize, GSMEM);
    cudaFuncSetAttribute(gemm_hmma_kernel<HID, false>,
                         cudaFuncAttributeMaxDynamicSharedMemorySize, GSMEM);
    cudaFuncSetAttribute(embw_kernel,
                         cudaFuncAttributeMaxDynamicSharedMemorySize, GSMEM);

    // 1) prep: deg + input conversion + W_emb transpose
    prep_kernel<<<PREP_BLOCKS, 256>>>(edges, node_in, W_emb);

    // 2) fused: embed GEMM + W1/W2/W3 transposes
    embw_kernel<<<EMBW_BLOCKS, GTHR, GSMEM>>>(HA, W + WOFF_E, b_emb, HB,
                                              W1, W2, W3, W);

    dim3 gg(HID / BN, N_NODES / BM);  // (4, 64)
    dim3 sg(N_NODES / 4);             // 2048 blocks

    // layer 1
    spmm_kernel<<<sg, 256>>>(edges, HB, HA);
    gemm_hmma_kernel<HID, true><<<gg, GTHR, GSMEM>>>(HA, W + WOFF_1, b1, HB, 1);
    // layer 2
    spmm_kernel<<<sg, 256>>>(edges, HB, HA);
    gemm_hmma_kernel<HID, true><<<gg, GTHR, GSMEM>>>(HA, W + WOFF_2, b2, HB, 1);
    // layer 3 -> fp32 out
    spmm_kernel<<<sg, 256>>>(edges, HB, HA);
    gemm_hmma_kernel<HID, false><<<gg, GTHR, GSMEM>>>(HA, W + WOFF_3, b3, out, 0);
}